// round 2
// baseline (speedup 1.0000x reference)
#include <cuda_runtime.h>
#include <cuda_fp16.h>
#include <cstdint>

// ---------------------------------------------------------------------------
// out[512, 65536] = inputs[512,256] @ features[65536,256]^T   (fp32 in/out)
//
// NOTE: the bench toolchain lowers through a compute_103 (non-'a') virtual
// arch, so tcgen05/TMEM PTX is rejected by ptxas. This kernel uses the
// baseline-PTX tensor path instead: ldmatrix + mma.sync.m16n8k16 (HMMA).
// The problem is memory-bound (192 MB DRAM floor ~27us vs ~8us HMMA issue),
// so the HMMA path costs little vs tcgen05.
//
// CTA tile: M=256 x N=128, K=256 fully resident in smem (fp32->fp16 fused
// conversion). 8 warps = 4(m) x 2(n), warp tile 64x64.
// Grid (2 m-supers, 512 n-blocks), m fast => features tile read once from
// DRAM, L2-shared by the 2 concurrent m CTAs.
// ---------------------------------------------------------------------------

#define ROWPAD 264            // 256 halves + 8 pad => 528B row stride (16B rot)
#define SMEM_BYTES ((256 + 128) * ROWPAD * 2)   // A:256 rows, B:128 rows

__device__ __forceinline__ uint32_t smem_u32(const void* p) {
    uint32_t a;
    asm("{ .reg .u64 t; cvta.to.shared.u64 t, %1; cvt.u32.u64 %0, t; }"
        : "=r"(a) : "l"(p));
    return a;
}

__device__ __forceinline__ void ldm_x4(uint32_t* r, uint32_t addr) {
    asm volatile(
        "ldmatrix.sync.aligned.m8n8.x4.shared.b16 {%0,%1,%2,%3}, [%4];"
        : "=r"(r[0]), "=r"(r[1]), "=r"(r[2]), "=r"(r[3]) : "r"(addr));
}

__device__ __forceinline__ void mma_16816(float* c, const uint32_t* a,
                                          uint32_t b0, uint32_t b1) {
    asm volatile(
        "mma.sync.aligned.m16n8k16.row.col.f32.f16.f16.f32 "
        "{%0,%1,%2,%3}, {%4,%5,%6,%7}, {%8,%9}, {%0,%1,%2,%3};"
        : "+f"(c[0]), "+f"(c[1]), "+f"(c[2]), "+f"(c[3])
        : "r"(a[0]), "r"(a[1]), "r"(a[2]), "r"(a[3]), "r"(b0), "r"(b1));
}

__global__ void __launch_bounds__(256, 1) hm_fwd_gemm_kernel(
    const float* __restrict__ inputs,    // [512, 256]
    const float* __restrict__ features,  // [65536, 256]
    float* __restrict__ out)             // [512, 65536]
{
    extern __shared__ char smem[];
    const uint32_t sA = smem_u32(smem);                       // 256 x 264 halves
    const uint32_t sB = sA + 256u * ROWPAD * 2u;              // 128 x 264 halves

    const int tid = threadIdx.x;
    const int wid = tid >> 5;
    const int lid = tid & 31;
    const int m_super = blockIdx.x;   // 0..1   (rows m_super*256 .. +256)
    const int n_blk   = blockIdx.y;   // 0..511 (feature rows n_blk*128 .. +128)

    // ---- Convert A tile: inputs[m_super*256 .. +256, :] f32 -> f16 smem ----
    {
        const float4* Ag = reinterpret_cast<const float4*>(inputs) + m_super * 16384;
#pragma unroll 8
        for (int it = 0; it < 64; ++it) {
            int fi = it * 256 + tid;            // coalesced float4 index
            float4 v = Ag[fi];
            int row = fi >> 6;                  // 64 float4 per row
            int c4  = fi & 63;
            uint32_t addr = sA + (uint32_t)(row * ROWPAD + c4 * 4) * 2u;
            __half2 h0 = __floats2half2_rn(v.x, v.y);
            __half2 h1 = __floats2half2_rn(v.z, v.w);
            asm volatile("st.shared.v2.b32 [%0], {%1, %2};"
                         :: "r"(addr),
                            "r"(*reinterpret_cast<uint32_t*>(&h0)),
                            "r"(*reinterpret_cast<uint32_t*>(&h1)));
        }
    }
    // ---- Convert B tile: features[n_blk*128 .. +128, :] f32 -> f16 smem ----
    {
        const float4* Bg = reinterpret_cast<const float4*>(features)
                         + (size_t)n_blk * 128 * 64;
#pragma unroll 8
        for (int it = 0; it < 32; ++it) {
            int fi = it * 256 + tid;
            float4 v = Bg[fi];
            int row = fi >> 6;
            int c4  = fi & 63;
            uint32_t addr = sB + (uint32_t)(row * ROWPAD + c4 * 4) * 2u;
            __half2 h0 = __floats2half2_rn(v.x, v.y);
            __half2 h1 = __floats2half2_rn(v.z, v.w);
            asm volatile("st.shared.v2.b32 [%0], {%1, %2};"
                         :: "r"(addr),
                            "r"(*reinterpret_cast<uint32_t*>(&h0)),
                            "r"(*reinterpret_cast<uint32_t*>(&h1)));
        }
    }
    __syncthreads();

    // ---- Compute: warp (wm, wn) owns a 64x64 tile of the 256x128 CTA tile ----
    const int wm = wid >> 1;   // 0..3
    const int wn = wid & 1;    // 0..1

    float acc[4][8][4];
#pragma unroll
    for (int mf = 0; mf < 4; ++mf)
#pragma unroll
        for (int nf = 0; nf < 8; ++nf)
#pragma unroll
            for (int e = 0; e < 4; ++e) acc[mf][nf][e] = 0.0f;

    // Precompute per-lane ldmatrix address components
    const int a_row_l = (lid & 15);          // row within m16 frag
    const int a_koff_l = (lid >> 4) * 8;     // k half-select
    const int b_nrow_l = (lid & 7) + ((lid >> 4) * 8);  // n row within n16 grp
    const int b_koff_l = ((lid >> 3) & 1) * 8;

    for (int ks = 0; ks < 16; ++ks) {
        const int kbase = ks * 16;
        uint32_t a[4][4];
#pragma unroll
        for (int mf = 0; mf < 4; ++mf) {
            int row = wm * 64 + mf * 16 + a_row_l;
            uint32_t addr = sA + (uint32_t)(row * ROWPAD + kbase + a_koff_l) * 2u;
            ldm_x4(a[mf], addr);
        }
        uint32_t b[4][4];
#pragma unroll
        for (int ng = 0; ng < 4; ++ng) {     // each x4 covers 16 n-rows
            int nrow = wn * 64 + ng * 16 + b_nrow_l;
            uint32_t addr = sB + (uint32_t)(nrow * ROWPAD + kbase + b_koff_l) * 2u;
            ldm_x4(b[ng], addr);
        }
#pragma unroll
        for (int mf = 0; mf < 4; ++mf)
#pragma unroll
            for (int nf = 0; nf < 8; ++nf)
                mma_16816(acc[mf][nf], a[mf],
                          b[nf >> 1][(nf & 1) * 2 + 0],
                          b[nf >> 1][(nf & 1) * 2 + 1]);
    }

    // ---- Epilogue: direct GMEM stores (32B-aligned float2 sectors) ----
    const int row0 = m_super * 256 + wm * 64 + (lid >> 2);
    const int col0 = n_blk * 128 + wn * 64 + (lid & 3) * 2;
#pragma unroll
    for (int mf = 0; mf < 4; ++mf) {
#pragma unroll
        for (int nf = 0; nf < 8; ++nf) {
            const int r = row0 + mf * 16;
            const int c = col0 + nf * 8;
            float2 v0 = make_float2(acc[mf][nf][0], acc[mf][nf][1]);
            float2 v1 = make_float2(acc[mf][nf][2], acc[mf][nf][3]);
            *reinterpret_cast<float2*>(out + (size_t)r * 65536 + c) = v0;
            *reinterpret_cast<float2*>(out + (size_t)(r + 8) * 65536 + c) = v1;
        }
    }
}

extern "C" void kernel_launch(void* const* d_in, const int* in_sizes, int n_in,
                              void* d_out, int out_size) {
    // metadata order: inputs f32[512,256], indexes i64[512],
    //                 features f32[65536,256], mIoU f32[65536], IoU f32[512];
    //                 output f32[512,65536]
    const float* inputs   = (const float*)d_in[0];
    const float* features = (const float*)d_in[2];
    float* out = (float*)d_out;

    cudaFuncSetAttribute(hm_fwd_gemm_kernel,
                         cudaFuncAttributeMaxDynamicSharedMemorySize, SMEM_BYTES);
    // grid.x = m_super (fast) so the 2 CTAs sharing a features tile run together
    hm_fwd_gemm_kernel<<<dim3(2, 512), 256, SMEM_BYTES>>>(inputs, features, out);
}

// round 3
// speedup vs baseline: 1.2190x; 1.2190x over previous
#include <cuda_runtime.h>
#include <cuda_fp16.h>
#include <cstdint>

// ---------------------------------------------------------------------------
// out[512, 65536] = inputs[512,256] @ features[65536,256]^T   (fp32 in/out)
//
// Toolchain constraint: harness compiles via compute_103 (non-'a') virtual
// arch, so tcgen05/TMEM PTX is unavailable. Tensor path = ldmatrix +
// mma.sync.m16n8k16 (HMMA).
//
// Two kernels:
//  1) convert_kernel: fp32 -> fp16 streaming pass into __device__ globals
//     (features 64MB->32MB, inputs 512KB->256KB). Run once per launch.
//  2) gemm_kernel: persistent 148 CTAs, tile M=128 x N=128 x K=256 smem-
//     resident fp16 (XOR-swizzled, no padding), cp.async double-buffered B
//     tiles prefetched 2 iterations ahead, 8 warps @ 64x32 warp tiles.
// ---------------------------------------------------------------------------

#define GY 37                       // grid.y; 4*37 = 148 CTAs (1/SM)
#define SMEM_BYTES (3 * 65536)      // A 64KB + B double buffer 2x64KB

__device__ __align__(256) __half g_fB[65536 * 256];  // features fp16
__device__ __align__(256) __half g_fA[512 * 256];    // inputs fp16

// ---------------- convert: fp32 -> fp16 streaming ----------------
__global__ void __launch_bounds__(256) convert_kernel(
    const float* __restrict__ features, const float* __restrict__ inputs)
{
    const int stride = gridDim.x * blockDim.x;
    const float4* f4 = reinterpret_cast<const float4*>(features);
    uint2* b4 = reinterpret_cast<uint2*>(g_fB);
    for (int i = blockIdx.x * blockDim.x + threadIdx.x; i < 4194304; i += stride) {
        float4 v = f4[i];
        __half2 h0 = __floats2half2_rn(v.x, v.y);
        __half2 h1 = __floats2half2_rn(v.z, v.w);
        b4[i] = make_uint2(*reinterpret_cast<uint32_t*>(&h0),
                           *reinterpret_cast<uint32_t*>(&h1));
    }
    const float4* i4 = reinterpret_cast<const float4*>(inputs);
    uint2* a4 = reinterpret_cast<uint2*>(g_fA);
    for (int i = blockIdx.x * blockDim.x + threadIdx.x; i < 32768; i += stride) {
        float4 v = i4[i];
        __half2 h0 = __floats2half2_rn(v.x, v.y);
        __half2 h1 = __floats2half2_rn(v.z, v.w);
        a4[i] = make_uint2(*reinterpret_cast<uint32_t*>(&h0),
                           *reinterpret_cast<uint32_t*>(&h1));
    }
}

// ---------------- gemm helpers ----------------
__device__ __forceinline__ uint32_t smem_u32(const void* p) {
    uint32_t a;
    asm("{ .reg .u64 t; cvta.to.shared.u64 t, %1; cvt.u32.u64 %0, t; }"
        : "=r"(a) : "l"(p));
    return a;
}

// Row = 512B (256 halves). Swizzle: XOR 16B-chunk index with (row & 7)
// -> conflict-free ldmatrix (8 rows hit 8 distinct 16B banks groups).
__device__ __forceinline__ uint32_t swz(uint32_t off) {
    return off ^ (((off >> 9) & 7u) << 4);
}

__device__ __forceinline__ void cp16(uint32_t dst, const void* src) {
    asm volatile("cp.async.cg.shared.global [%0], [%1], 16;"
                 :: "r"(dst), "l"(src));
}

__device__ __forceinline__ void ldm_x4(uint32_t* r, uint32_t addr) {
    asm volatile(
        "ldmatrix.sync.aligned.m8n8.x4.shared.b16 {%0,%1,%2,%3}, [%4];"
        : "=r"(r[0]), "=r"(r[1]), "=r"(r[2]), "=r"(r[3]) : "r"(addr));
}

__device__ __forceinline__ void mma_16816(float* c, const uint32_t* a,
                                          uint32_t b0, uint32_t b1) {
    asm volatile(
        "mma.sync.aligned.m16n8k16.row.col.f32.f16.f16.f32 "
        "{%0,%1,%2,%3}, {%4,%5,%6,%7}, {%8,%9}, {%0,%1,%2,%3};"
        : "+f"(c[0]), "+f"(c[1]), "+f"(c[2]), "+f"(c[3])
        : "r"(a[0]), "r"(a[1]), "r"(a[2]), "r"(a[3]), "r"(b0), "r"(b1));
}

// Issue cp.async for a full 128x256-half tile (64KB) into swizzled smem.
__device__ __forceinline__ void issue_tile_copy(uint32_t sdst,
                                                const __half* gsrc, int tid) {
#pragma unroll 4
    for (int q = tid; q < 4096; q += 256) {
        int row = q >> 5;        // 32 x 16B chunks per 512B row
        int c   = q & 31;
        cp16(sdst + swz((uint32_t)(row * 512 + c * 16)),
             gsrc + row * 256 + c * 8);
    }
}

__global__ void __launch_bounds__(256, 1) gemm_kernel(float* __restrict__ out)
{
    extern __shared__ char smem[];
    const uint32_t sA  = smem_u32(smem);       // 128 x 512B
    const uint32_t sB0 = sA + 65536u;
    const uint32_t sB1 = sA + 131072u;

    const int tid = threadIdx.x;
    const int wid = tid >> 5;
    const int lid = tid & 31;
    const int wm = wid >> 2;    // 0..1  (64 m-rows each)
    const int wn = wid & 3;     // 0..3  (32 n-rows each)
    const int m_super = blockIdx.x;   // 0..3  (rows m_super*128 .. +128)
    const int j0 = blockIdx.y;        // first n-block; stride GY

    // Prologue: A tile + first two B tiles in flight (3 commit groups).
    issue_tile_copy(sA, g_fA + m_super * 128 * 256, tid);
    asm volatile("cp.async.commit_group;");
    issue_tile_copy(sB0, g_fB + (size_t)j0 * 128 * 256, tid);
    asm volatile("cp.async.commit_group;");
    issue_tile_copy(sB1, g_fB + (size_t)(j0 + GY) * 128 * 256, tid);
    asm volatile("cp.async.commit_group;");

    // Per-lane ldmatrix address components
    const int a_row = lid & 15;
    const int a_kb  = (lid >> 4) * 16;                 // bytes
    const int b_row = (lid & 7) + ((lid >> 4) * 8);
    const int b_kb  = ((lid >> 3) & 1) * 16;           // bytes

    int parity = 0;
    for (int j = j0; j < 512; j += GY) {
        asm volatile("cp.async.wait_group 1;");
        __syncthreads();
        const uint32_t sB = parity ? sB1 : sB0;

        float acc[4][4][4];
#pragma unroll
        for (int mf = 0; mf < 4; ++mf)
#pragma unroll
            for (int nf = 0; nf < 4; ++nf)
#pragma unroll
                for (int e = 0; e < 4; ++e) acc[mf][nf][e] = 0.0f;

#pragma unroll
        for (int ks = 0; ks < 16; ++ks) {
            const uint32_t kb = ks * 32;   // 16 halves = 32B per k-step
            uint32_t a[4][4];
#pragma unroll
            for (int mf = 0; mf < 4; ++mf) {
                int row = wm * 64 + mf * 16 + a_row;
                ldm_x4(a[mf], sA + swz((uint32_t)(row * 512) + kb + a_kb));
            }
            uint32_t b[2][4];
#pragma unroll
            for (int ng = 0; ng < 2; ++ng) {
                int nrow = wn * 32 + ng * 16 + b_row;
                ldm_x4(b[ng], sB + swz((uint32_t)(nrow * 512) + kb + b_kb));
            }
#pragma unroll
            for (int mf = 0; mf < 4; ++mf)
#pragma unroll
                for (int nf = 0; nf < 4; ++nf)
                    mma_16816(acc[mf][nf], a[mf],
                              b[nf >> 1][(nf & 1) * 2 + 0],
                              b[nf >> 1][(nf & 1) * 2 + 1]);
        }

        __syncthreads();   // all warps done reading sB(parity)

        // Prefetch B tile j + 2*GY into the buffer just freed; overlaps
        // epilogue stores and the next iteration's MMA.
        int pf = j + 2 * GY;
        if (pf < 512)
            issue_tile_copy(parity ? sB1 : sB0,
                            g_fB + (size_t)pf * 128 * 256, tid);
        asm volatile("cp.async.commit_group;");

        // Epilogue: direct GMEM float2 stores
        const int row0 = m_super * 128 + wm * 64 + (lid >> 2);
        const int col0 = j * 128 + wn * 32 + (lid & 3) * 2;
#pragma unroll
        for (int mf = 0; mf < 4; ++mf) {
#pragma unroll
            for (int nf = 0; nf < 4; ++nf) {
                const int r = row0 + mf * 16;
                const int c = col0 + nf * 8;
                float2 v0 = make_float2(acc[mf][nf][0], acc[mf][nf][1]);
                float2 v1 = make_float2(acc[mf][nf][2], acc[mf][nf][3]);
                *reinterpret_cast<float2*>(out + (size_t)r * 65536 + c) = v0;
                *reinterpret_cast<float2*>(out + (size_t)(r + 8) * 65536 + c) = v1;
            }
        }
        parity ^= 1;
    }
}

extern "C" void kernel_launch(void* const* d_in, const int* in_sizes, int n_in,
                              void* d_out, int out_size) {
    // metadata order: inputs f32[512,256], indexes i64[512],
    //                 features f32[65536,256], mIoU f32[65536], IoU f32[512];
    //                 output f32[512,65536]
    const float* inputs   = (const float*)d_in[0];
    const float* features = (const float*)d_in[2];
    float* out = (float*)d_out;

    convert_kernel<<<1184, 256>>>(features, inputs);

    cudaFuncSetAttribute(gemm_kernel,
                         cudaFuncAttributeMaxDynamicSharedMemorySize, SMEM_BYTES);
    // grid.x = m_super (fast): the 4 CTAs sharing each B tile run concurrently
    gemm_kernel<<<dim3(4, GY), 256, SMEM_BYTES>>>(out);
}